// round 12
// baseline (speedup 1.0000x reference)
#include <cuda_runtime.h>

// FourierConv2D via DFT-as-GEMM (fp32 FFMA) with five symmetry folds (~6.4 GFLOP):
//  1) real input => only ky=0..255 of the 511-row spectrum
//  2) forward col-DFT: P/Q shared-product pairs give F(kx), F(511-kx) together
//  3) inverse col-DFT K-fold: S=G+G', D=G-G' => K=256
//  4) inverse col-DFT x-fold: distinct x=0..127 (+tail 128/129), partner 257-t
//  5) row-inverse y-fold: distinct y=0..127 (+tail 128/129)
// R12: tensor stage4 reverted (legacy HMMA is issue-bound, slower than FFMA).
// All four GEMM mainloops double-buffered: prefetch chunk c+1 into registers
// while computing chunk c; ONE __syncthreads per chunk (was two).

namespace {
constexpr int N5    = 511;
constexpr int HH    = 256;
constexpr int NB    = 4;
constexpr int NCIN  = 4;
constexpr int NCOUT = 8;
constexpr int PLANE = N5 * N5;
constexpr int SQ    = HH * HH;       // 65536
constexpr int BC    = NB * NCIN;     // 16
constexpr int BO    = NB * NCOUT;    // 32
}

// ---- scratch (device globals) ----
__device__ float  g_Ar[SQ],  g_Ai[SQ];   // A[kx][n] = exp(-2pi i kx n/511)
__device__ float2 g_E[SQ];               // {Er,Ei}[x][kx] = exp(+2pi i kx (x+127)/511)/511
__device__ float  g_E5r[SQ], g_E5i[SQ];  // E5[y][ky] = w(ky) exp(+2pi i ky (y+127)/511)
__device__ float  g_T1r[BC*SQ], g_T1i[BC*SQ];
__device__ float2 g_P[BC*SQ], g_Q[BC*SQ];   // F(kx), F(511-kx), kx=0..255
__device__ float4 g_SD[BO*SQ];              // {Sr,Si,Dr,Di}[ky][kx]
__device__ float  g_T2r[BO*SQ], g_T2i[BO*SQ];

// ---- twiddle init ----
__global__ void k_twiddle() {
    const int idx = blockIdx.x * blockDim.x + threadIdx.x;   // 0..65535
    const float TWO_PI = 6.283185307179586f;
    const int r = idx >> 8, c = idx & 255;
    {   int m = (r * c) % N5;
        float s, co; sincosf(TWO_PI * (float)m / (float)N5, &s, &co);
        g_Ar[idx] = co;  g_Ai[idx] = -s;
    }
    {   int m = (c * (r + 127)) % N5;
        float s, co; sincosf(TWO_PI * (float)m / (float)N5, &s, &co);
        const float inv = 1.0f / (float)N5;
        g_E[idx] = make_float2(co * inv, s * inv);
    }
    {   int m = (c * (r + 127)) % N5;
        float s, co; sincosf(TWO_PI * (float)m / (float)N5, &s, &co);
        const float w = (c == 0) ? (1.0f / (float)N5) : (2.0f / (float)N5);
        g_E5r[idx] = co * w;  g_E5i[idx] = s * w;
    }
}

// All GEMM kernels: 32x32 tile (stage4: 32x32 over folded cols), 128 threads,
// K-chunk 16, double-buffered smem, one sync per chunk.

// ---- stage 1: T1[z] (256x256 cplx) = A[0:256] (cplx) @ X[z] (256x256 real) ----
__global__ void __launch_bounds__(128) k_stage1(const float* __restrict__ im) {
    const int z = blockIdx.z;
    const float* __restrict__ X = im + (size_t)z * SQ;
    float* __restrict__ Cr = g_T1r + (size_t)z * SQ;
    float* __restrict__ Ci = g_T1i + (size_t)z * SQ;

    __shared__ float Asr[2][16][36], Asi[2][16][36], Bs[2][16][36];
    const int tid = threadIdx.x;
    const int tx = tid & 15, ty = tid >> 4;
    const int m0 = blockIdx.y * 32, n0 = blockIdx.x * 32;
    const int ra = tid >> 2, ka = (tid & 3) * 4;
    const int kb = tid >> 3, nb = (tid & 7) * 4;

    float4 arv = *reinterpret_cast<const float4*>(g_Ar + (size_t)(m0 + ra)*HH + ka);
    float4 aiv = *reinterpret_cast<const float4*>(g_Ai + (size_t)(m0 + ra)*HH + ka);
    float4 bv  = *reinterpret_cast<const float4*>(X + (size_t)kb*HH + n0 + nb);
    Asr[0][ka+0][ra]=arv.x; Asr[0][ka+1][ra]=arv.y; Asr[0][ka+2][ra]=arv.z; Asr[0][ka+3][ra]=arv.w;
    Asi[0][ka+0][ra]=aiv.x; Asi[0][ka+1][ra]=aiv.y; Asi[0][ka+2][ra]=aiv.z; Asi[0][ka+3][ra]=aiv.w;
    Bs[0][kb][nb+0]=bv.x; Bs[0][kb][nb+1]=bv.y; Bs[0][kb][nb+2]=bv.z; Bs[0][kb][nb+3]=bv.w;
    __syncthreads();

    float cr[4][2] = {}, ci[4][2] = {};

    for (int c = 0; c < 16; c++) {
        const int cur = c & 1;
        if (c < 15) {
            const int k0 = (c + 1) * 16;
            arv = *reinterpret_cast<const float4*>(g_Ar + (size_t)(m0 + ra)*HH + k0 + ka);
            aiv = *reinterpret_cast<const float4*>(g_Ai + (size_t)(m0 + ra)*HH + k0 + ka);
            bv  = *reinterpret_cast<const float4*>(X + (size_t)(k0 + kb)*HH + n0 + nb);
        }
        #pragma unroll 4
        for (int k = 0; k < 16; k++) {
            float4 a_r = *reinterpret_cast<const float4*>(&Asr[cur][k][ty*4]);
            float4 a_i = *reinterpret_cast<const float4*>(&Asi[cur][k][ty*4]);
            float2 b   = *reinterpret_cast<const float2*>(&Bs[cur][k][tx*2]);
            const float ar[4] = {a_r.x, a_r.y, a_r.z, a_r.w};
            const float ai[4] = {a_i.x, a_i.y, a_i.z, a_i.w};
            const float bb[2] = {b.x, b.y};
            #pragma unroll
            for (int i = 0; i < 4; i++)
                #pragma unroll
                for (int j = 0; j < 2; j++) {
                    cr[i][j] += ar[i] * bb[j];
                    ci[i][j] += ai[i] * bb[j];
                }
        }
        if (c < 15) {
            const int nxt = cur ^ 1;
            Asr[nxt][ka+0][ra]=arv.x; Asr[nxt][ka+1][ra]=arv.y; Asr[nxt][ka+2][ra]=arv.z; Asr[nxt][ka+3][ra]=arv.w;
            Asi[nxt][ka+0][ra]=aiv.x; Asi[nxt][ka+1][ra]=aiv.y; Asi[nxt][ka+2][ra]=aiv.z; Asi[nxt][ka+3][ra]=aiv.w;
            Bs[nxt][kb][nb+0]=bv.x; Bs[nxt][kb][nb+1]=bv.y; Bs[nxt][kb][nb+2]=bv.z; Bs[nxt][kb][nb+3]=bv.w;
        }
        __syncthreads();
    }
    const int gn = n0 + tx*2;
    #pragma unroll
    for (int i = 0; i < 4; i++) {
        const int gm = m0 + ty*4 + i;
        *reinterpret_cast<float2*>(Cr + (size_t)gm*HH + gn) = make_float2(cr[i][0], cr[i][1]);
        *reinterpret_cast<float2*>(Ci + (size_t)gm*HH + gn) = make_float2(ci[i][0], ci[i][1]);
    }
}

// ---- stage 2: P,Q[z][ky][kx] via shared products U/V/X/Y ----
// P = (U-V, X+Y) = F(kx);  Q = (U+V, Y-X) = F(511-kx)
__global__ void __launch_bounds__(128) k_stage2() {
    const int z = blockIdx.z;
    const float* __restrict__ T1r = g_T1r + (size_t)z * SQ;
    const float* __restrict__ T1i = g_T1i + (size_t)z * SQ;
    float2* __restrict__ P = g_P + (size_t)z * SQ;
    float2* __restrict__ Q = g_Q + (size_t)z * SQ;

    __shared__ float Asr[2][16][36], Asi[2][16][36], Bsr[2][16][36], Bsi[2][16][36];
    const int tid = threadIdx.x;
    const int tx = tid & 15, ty = tid >> 4;
    const int m0 = blockIdx.y * 32, n0 = blockIdx.x * 32;
    const int ra = tid >> 2, ka = (tid & 3) * 4;

    float4 arv = *reinterpret_cast<const float4*>(T1r + (size_t)(m0 + ra)*HH + ka);
    float4 aiv = *reinterpret_cast<const float4*>(T1i + (size_t)(m0 + ra)*HH + ka);
    float4 brv = *reinterpret_cast<const float4*>(g_Ar + (size_t)(n0 + ra)*HH + ka);
    float4 biv = *reinterpret_cast<const float4*>(g_Ai + (size_t)(n0 + ra)*HH + ka);
    Asr[0][ka+0][ra]=arv.x; Asr[0][ka+1][ra]=arv.y; Asr[0][ka+2][ra]=arv.z; Asr[0][ka+3][ra]=arv.w;
    Asi[0][ka+0][ra]=aiv.x; Asi[0][ka+1][ra]=aiv.y; Asi[0][ka+2][ra]=aiv.z; Asi[0][ka+3][ra]=aiv.w;
    Bsr[0][ka+0][ra]=brv.x; Bsr[0][ka+1][ra]=brv.y; Bsr[0][ka+2][ra]=brv.z; Bsr[0][ka+3][ra]=brv.w;
    Bsi[0][ka+0][ra]=biv.x; Bsi[0][ka+1][ra]=biv.y; Bsi[0][ka+2][ra]=biv.z; Bsi[0][ka+3][ra]=biv.w;
    __syncthreads();

    float U[4][2] = {}, V[4][2] = {}, Xc[4][2] = {}, Yc[4][2] = {};

    for (int c = 0; c < 16; c++) {
        const int cur = c & 1;
        if (c < 15) {
            const int k0 = (c + 1) * 16;
            arv = *reinterpret_cast<const float4*>(T1r + (size_t)(m0 + ra)*HH + k0 + ka);
            aiv = *reinterpret_cast<const float4*>(T1i + (size_t)(m0 + ra)*HH + k0 + ka);
            brv = *reinterpret_cast<const float4*>(g_Ar + (size_t)(n0 + ra)*HH + k0 + ka);
            biv = *reinterpret_cast<const float4*>(g_Ai + (size_t)(n0 + ra)*HH + k0 + ka);
        }
        #pragma unroll 4
        for (int k = 0; k < 16; k++) {
            float4 a_r = *reinterpret_cast<const float4*>(&Asr[cur][k][ty*4]);
            float4 a_i = *reinterpret_cast<const float4*>(&Asi[cur][k][ty*4]);
            float2 b_r = *reinterpret_cast<const float2*>(&Bsr[cur][k][tx*2]);
            float2 b_i = *reinterpret_cast<const float2*>(&Bsi[cur][k][tx*2]);
            const float ar[4] = {a_r.x, a_r.y, a_r.z, a_r.w};
            const float ai[4] = {a_i.x, a_i.y, a_i.z, a_i.w};
            const float wr[2] = {b_r.x, b_r.y};
            const float wi[2] = {b_i.x, b_i.y};
            #pragma unroll
            for (int i = 0; i < 4; i++)
                #pragma unroll
                for (int j = 0; j < 2; j++) {
                    U [i][j] += ar[i] * wr[j];
                    V [i][j] += ai[i] * wi[j];
                    Xc[i][j] += ar[i] * wi[j];
                    Yc[i][j] += ai[i] * wr[j];
                }
        }
        if (c < 15) {
            const int nxt = cur ^ 1;
            Asr[nxt][ka+0][ra]=arv.x; Asr[nxt][ka+1][ra]=arv.y; Asr[nxt][ka+2][ra]=arv.z; Asr[nxt][ka+3][ra]=arv.w;
            Asi[nxt][ka+0][ra]=aiv.x; Asi[nxt][ka+1][ra]=aiv.y; Asi[nxt][ka+2][ra]=aiv.z; Asi[nxt][ka+3][ra]=aiv.w;
            Bsr[nxt][ka+0][ra]=brv.x; Bsr[nxt][ka+1][ra]=brv.y; Bsr[nxt][ka+2][ra]=brv.z; Bsr[nxt][ka+3][ra]=brv.w;
            Bsi[nxt][ka+0][ra]=biv.x; Bsi[nxt][ka+1][ra]=biv.y; Bsi[nxt][ka+2][ra]=biv.z; Bsi[nxt][ka+3][ra]=biv.w;
        }
        __syncthreads();
    }
    const int gn = n0 + tx*2;
    #pragma unroll
    for (int i = 0; i < 4; i++) {
        const int gm = m0 + ty*4 + i;
        float4 pv = make_float4(U[i][0]-V[i][0], Xc[i][0]+Yc[i][0],
                                U[i][1]-V[i][1], Xc[i][1]+Yc[i][1]);
        float4 qv = make_float4(U[i][0]+V[i][0], Yc[i][0]-Xc[i][0],
                                U[i][1]+V[i][1], Yc[i][1]-Xc[i][1]);
        *reinterpret_cast<float4*>(P + (size_t)gm*HH + gn) = pv;
        *reinterpret_cast<float4*>(Q + (size_t)gm*HH + gn) = qv;
    }
}

// ---- stage 3: pointwise Hermitian-W multiply + cin sum + S/D combine ----
__global__ void k_pointwise(const float* __restrict__ w) {
    const int p = blockIdx.x * blockDim.x + threadIdx.x;  // ky*256+kx
    const int o = blockIdx.y;
    const int ky = p >> 8, kx = p & 255;
    const int ky2 = (N5 - ky) % N5;
    const int kx2 = (N5 - kx) % N5;

    float2 wh1[NCIN], wh2[NCIN];
    #pragma unroll
    for (int c = 0; c < NCIN; c++) {
        const float* wb = w + (size_t)(o*NCIN + c) * PLANE * 2;
        const float2 a = *reinterpret_cast<const float2*>(wb + ((size_t)ky *N5 + kx )*2);
        const float2 bq= *reinterpret_cast<const float2*>(wb + ((size_t)ky2*N5 + kx2)*2);
        wh1[c] = make_float2(0.5f*(a.x + bq.x), 0.5f*(a.y - bq.y));
        if (kx != 0) {
            const float2 e = *reinterpret_cast<const float2*>(wb + ((size_t)ky *N5 + (N5-kx))*2);
            const float2 f = *reinterpret_cast<const float2*>(wb + ((size_t)ky2*N5 + kx     )*2);
            wh2[c] = make_float2(0.5f*(e.x + f.x), 0.5f*(e.y - f.y));
        } else {
            wh2[c] = make_float2(0.f, 0.f);
        }
    }
    #pragma unroll
    for (int b = 0; b < NB; b++) {
        float gr = 0.f, gi = 0.f, hr = 0.f, hi = 0.f;
        #pragma unroll
        for (int c = 0; c < NCIN; c++) {
            const float2 Pv = g_P[(size_t)(b*NCIN + c)*SQ + p];
            const float2 Qv = g_Q[(size_t)(b*NCIN + c)*SQ + p];
            gr += Pv.x * wh1[c].x - Pv.y * wh1[c].y;
            gi += Pv.x * wh1[c].y + Pv.y * wh1[c].x;
            hr += Qv.x * wh2[c].x - Qv.y * wh2[c].y;
            hi += Qv.x * wh2[c].y + Qv.y * wh2[c].x;
        }
        g_SD[(size_t)(b*NCOUT + o)*SQ + p] =
            make_float4(gr + hr, gi + hi, gr - hr, gi - hi);
    }
}

// ---- stage 4 (x-folded): distinct cols t=0..127, partners x=257-t (t>=2) ----
// P=Sum Sr*Er, Q=Sum Di*Ei, R=Sum Si*Er, T=Sum Dr*Ei  over kx
// T2[ky][t] = (P-Q, R+T);  T2[ky][257-t] = (P+Q, R-T)
__global__ void __launch_bounds__(128) k_stage4() {
    const int z = blockIdx.z;
    const float4* __restrict__ Ag = g_SD + (size_t)z * SQ;
    float* __restrict__ Cr = g_T2r + (size_t)z * SQ;
    float* __restrict__ Ci = g_T2i + (size_t)z * SQ;

    __shared__ float4 As4[2][16][33];    // float4 elems -> 16B aligned
    __shared__ float2 Bs2[2][16][34];    // row 272B = 17*16 (float4-read safe)
    const int tid = threadIdx.x;
    const int tx = tid & 15, ty = tid >> 4;
    const int m0 = blockIdx.y * 32, n0 = blockIdx.x * 32;
    const int ra = tid >> 2, ka = (tid & 3) * 4;

    float4 av[4], e01, e23;
    #pragma unroll
    for (int j = 0; j < 4; j++) av[j] = Ag[(size_t)(m0 + ra)*HH + ka + j];
    {   const float4* src = reinterpret_cast<const float4*>(g_E + (size_t)(n0 + ra)*HH + ka);
        e01 = src[0]; e23 = src[1];
    }
    #pragma unroll
    for (int j = 0; j < 4; j++) As4[0][ka + j][ra] = av[j];
    Bs2[0][ka+0][ra] = make_float2(e01.x, e01.y);
    Bs2[0][ka+1][ra] = make_float2(e01.z, e01.w);
    Bs2[0][ka+2][ra] = make_float2(e23.x, e23.y);
    Bs2[0][ka+3][ra] = make_float2(e23.z, e23.w);
    __syncthreads();

    float P[4][2] = {}, Q[4][2] = {}, R[4][2] = {}, T[4][2] = {};

    for (int c = 0; c < 16; c++) {
        const int cur = c & 1;
        if (c < 15) {
            const int k0 = (c + 1) * 16;
            #pragma unroll
            for (int j = 0; j < 4; j++) av[j] = Ag[(size_t)(m0 + ra)*HH + k0 + ka + j];
            const float4* src = reinterpret_cast<const float4*>(g_E + (size_t)(n0 + ra)*HH + k0 + ka);
            e01 = src[0]; e23 = src[1];
        }
        #pragma unroll 2
        for (int k = 0; k < 16; k++) {
            float4 a[4];
            #pragma unroll
            for (int i = 0; i < 4; i++) a[i] = As4[cur][k][ty*4 + i];
            float4 bvec = *reinterpret_cast<const float4*>(&Bs2[cur][k][tx*2]);  // {Er0,Ei0,Er1,Ei1}
            const float er[2] = {bvec.x, bvec.z};
            const float ei[2] = {bvec.y, bvec.w};
            #pragma unroll
            for (int i = 0; i < 4; i++)
                #pragma unroll
                for (int j = 0; j < 2; j++) {
                    P[i][j] += a[i].x * er[j];   // Sr*Er
                    Q[i][j] += a[i].w * ei[j];   // Di*Ei
                    R[i][j] += a[i].y * er[j];   // Si*Er
                    T[i][j] += a[i].z * ei[j];   // Dr*Ei
                }
        }
        if (c < 15) {
            const int nxt = cur ^ 1;
            #pragma unroll
            for (int j = 0; j < 4; j++) As4[nxt][ka + j][ra] = av[j];
            Bs2[nxt][ka+0][ra] = make_float2(e01.x, e01.y);
            Bs2[nxt][ka+1][ra] = make_float2(e01.z, e01.w);
            Bs2[nxt][ka+2][ra] = make_float2(e23.x, e23.y);
            Bs2[nxt][ka+3][ra] = make_float2(e23.z, e23.w);
        }
        __syncthreads();
    }
    const int t0 = n0 + tx*2;
    #pragma unroll
    for (int i = 0; i < 4; i++) {
        const int gm = m0 + ty*4 + i;
        *reinterpret_cast<float2*>(Cr + (size_t)gm*HH + t0) =
            make_float2(P[i][0]-Q[i][0], P[i][1]-Q[i][1]);
        *reinterpret_cast<float2*>(Ci + (size_t)gm*HH + t0) =
            make_float2(R[i][0]+T[i][0], R[i][1]+T[i][1]);
        if (t0 >= 2) {
            *reinterpret_cast<float2*>(Cr + (size_t)gm*HH + 256 - t0) =
                make_float2(P[i][1]+Q[i][1], P[i][0]+Q[i][0]);
            *reinterpret_cast<float2*>(Ci + (size_t)gm*HH + 256 - t0) =
                make_float2(R[i][1]-T[i][1], R[i][0]-T[i][0]);
        }
    }
}

// ---- stage 4 tail: T2 cols 128,129 from E row 128 (129 = conj partner) ----
__global__ void k_tail4() {
    const int z = blockIdx.y;
    const int warp = threadIdx.x >> 5, lane = threadIdx.x & 31;
    const int ky = blockIdx.x * 8 + warp;
    const float4* __restrict__ Arow = g_SD + (size_t)z * SQ + (size_t)ky * HH;
    float P = 0.f, Q = 0.f, R = 0.f, T = 0.f;
    for (int kx = lane; kx < HH; kx += 32) {
        const float4 a = Arow[kx];
        const float2 e = g_E[128*HH + kx];
        P += a.x * e.x;  Q += a.w * e.y;
        R += a.y * e.x;  T += a.z * e.y;
    }
    #pragma unroll
    for (int off = 16; off; off >>= 1) {
        P += __shfl_down_sync(0xffffffffu, P, off);
        Q += __shfl_down_sync(0xffffffffu, Q, off);
        R += __shfl_down_sync(0xffffffffu, R, off);
        T += __shfl_down_sync(0xffffffffu, T, off);
    }
    if (lane == 0) {
        float* Cr = g_T2r + (size_t)z * SQ + (size_t)ky * HH;
        float* Ci = g_T2i + (size_t)z * SQ + (size_t)ky * HH;
        Cr[128] = P - Q;  Ci[128] = R + T;
        Cr[129] = P + Q;  Ci[129] = R - T;
    }
}

// ---- stage 5 (y-folded): distinct rows y=0..127, partners 257-y (y>=2) ----
// P=Sum E5r*T2r, Q=Sum E5i*T2i;  out[y]=P-Q+b;  out[257-y]=P+Q+b
__global__ void __launch_bounds__(128) k_stage5(const float* __restrict__ bias,
                                                float* __restrict__ out) {
    const int z = blockIdx.z;
    const float* __restrict__ Br = g_T2r + (size_t)z * SQ;
    const float* __restrict__ Bi = g_T2i + (size_t)z * SQ;
    float* __restrict__ O = out + (size_t)z * SQ;

    __shared__ float Asr[2][16][36], Asi[2][16][36], Bsr[2][16][36], Bsi[2][16][36];
    const int tid = threadIdx.x;
    const int tx = tid & 15, ty = tid >> 4;
    const int m0 = blockIdx.y * 32, n0 = blockIdx.x * 32;  // m0 in {0,32,64,96}
    const int ra = tid >> 2, ka = (tid & 3) * 4;
    const int kb = tid >> 3, nb = (tid & 7) * 4;

    float4 arv = *reinterpret_cast<const float4*>(g_E5r + (size_t)(m0 + ra)*HH + ka);
    float4 aiv = *reinterpret_cast<const float4*>(g_E5i + (size_t)(m0 + ra)*HH + ka);
    float4 brv = *reinterpret_cast<const float4*>(Br + (size_t)kb*HH + n0 + nb);
    float4 biv = *reinterpret_cast<const float4*>(Bi + (size_t)kb*HH + n0 + nb);
    Asr[0][ka+0][ra]=arv.x; Asr[0][ka+1][ra]=arv.y; Asr[0][ka+2][ra]=arv.z; Asr[0][ka+3][ra]=arv.w;
    Asi[0][ka+0][ra]=aiv.x; Asi[0][ka+1][ra]=aiv.y; Asi[0][ka+2][ra]=aiv.z; Asi[0][ka+3][ra]=aiv.w;
    Bsr[0][kb][nb+0]=brv.x; Bsr[0][kb][nb+1]=brv.y; Bsr[0][kb][nb+2]=brv.z; Bsr[0][kb][nb+3]=brv.w;
    Bsi[0][kb][nb+0]=biv.x; Bsi[0][kb][nb+1]=biv.y; Bsi[0][kb][nb+2]=biv.z; Bsi[0][kb][nb+3]=biv.w;
    __syncthreads();

    float P[4][2] = {}, Q[4][2] = {};

    for (int c = 0; c < 16; c++) {
        const int cur = c & 1;
        if (c < 15) {
            const int k0 = (c + 1) * 16;
            arv = *reinterpret_cast<const float4*>(g_E5r + (size_t)(m0 + ra)*HH + k0 + ka);
            aiv = *reinterpret_cast<const float4*>(g_E5i + (size_t)(m0 + ra)*HH + k0 + ka);
            brv = *reinterpret_cast<const float4*>(Br + (size_t)(k0 + kb)*HH + n0 + nb);
            biv = *reinterpret_cast<const float4*>(Bi + (size_t)(k0 + kb)*HH + n0 + nb);
        }
        #pragma unroll 4
        for (int k = 0; k < 16; k++) {
            float4 e_r = *reinterpret_cast<const float4*>(&Asr[cur][k][ty*4]);
            float4 e_i = *reinterpret_cast<const float4*>(&Asi[cur][k][ty*4]);
            float2 b_r = *reinterpret_cast<const float2*>(&Bsr[cur][k][tx*2]);
            float2 b_i = *reinterpret_cast<const float2*>(&Bsi[cur][k][tx*2]);
            const float er[4] = {e_r.x, e_r.y, e_r.z, e_r.w};
            const float ei[4] = {e_i.x, e_i.y, e_i.z, e_i.w};
            const float br[2] = {b_r.x, b_r.y};
            const float bi[2] = {b_i.x, b_i.y};
            #pragma unroll
            for (int i = 0; i < 4; i++)
                #pragma unroll
                for (int j = 0; j < 2; j++) {
                    P[i][j] += er[i] * br[j];
                    Q[i][j] += ei[i] * bi[j];
                }
        }
        if (c < 15) {
            const int nxt = cur ^ 1;
            Asr[nxt][ka+0][ra]=arv.x; Asr[nxt][ka+1][ra]=arv.y; Asr[nxt][ka+2][ra]=arv.z; Asr[nxt][ka+3][ra]=arv.w;
            Asi[nxt][ka+0][ra]=aiv.x; Asi[nxt][ka+1][ra]=aiv.y; Asi[nxt][ka+2][ra]=aiv.z; Asi[nxt][ka+3][ra]=aiv.w;
            Bsr[nxt][kb][nb+0]=brv.x; Bsr[nxt][kb][nb+1]=brv.y; Bsr[nxt][kb][nb+2]=brv.z; Bsr[nxt][kb][nb+3]=brv.w;
            Bsi[nxt][kb][nb+0]=biv.x; Bsi[nxt][kb][nb+1]=biv.y; Bsi[nxt][kb][nb+2]=biv.z; Bsi[nxt][kb][nb+3]=biv.w;
        }
        __syncthreads();
    }
    const float bv = bias[z & 7];
    const int gn = n0 + tx*2;
    #pragma unroll
    for (int i = 0; i < 4; i++) {
        const int gm = m0 + ty*4 + i;   // 0..127
        *reinterpret_cast<float2*>(&O[(size_t)gm*HH + gn]) =
            make_float2(P[i][0]-Q[i][0] + bv, P[i][1]-Q[i][1] + bv);
        if (gm >= 2) {
            *reinterpret_cast<float2*>(&O[(size_t)(257 - gm)*HH + gn]) =
                make_float2(P[i][0]+Q[i][0] + bv, P[i][1]+Q[i][1] + bv);
        }
    }
}

// ---- stage 5 tail: out rows 128,129 from E5 row 128 (129 = conj partner) ----
__global__ void k_tail5(const float* __restrict__ bias, float* __restrict__ out) {
    const int z = blockIdx.x;
    const int n = threadIdx.x;
    const float* __restrict__ Br = g_T2r + (size_t)z * SQ;
    const float* __restrict__ Bi = g_T2i + (size_t)z * SQ;
    float P = 0.f, Q = 0.f;
    for (int ky = 0; ky < HH; ky++) {
        P += g_E5r[128*HH + ky] * Br[(size_t)ky*HH + n];
        Q += g_E5i[128*HH + ky] * Bi[(size_t)ky*HH + n];
    }
    const float bv = bias[z & 7];
    out[(size_t)z*SQ + 128*HH + n] = P - Q + bv;
    out[(size_t)z*SQ + 129*HH + n] = P + Q + bv;
}

extern "C" void kernel_launch(void* const* d_in, const int* in_sizes, int n_in,
                              void* d_out, int out_size) {
    (void)in_sizes; (void)n_in; (void)out_size;
    const float* im   = (const float*)d_in[0];  // [4,4,256,256]
    const float* w    = (const float*)d_in[1];  // [8,4,511,511,2]
    const float* bias = (const float*)d_in[2];  // [8,1,1]
    float* out = (float*)d_out;                 // [4,8,256,256]

    k_twiddle<<<256, 256>>>();
    k_stage1 <<<dim3(8, 8, BC), 128>>>(im);            // 1024 blocks
    k_stage2 <<<dim3(8, 8, BC), 128>>>();              // 1024 blocks
    k_pointwise<<<dim3(SQ / 256, NCOUT), 256>>>(w);
    k_stage4 <<<dim3(4, 8, BO), 128>>>();              // 1024 blocks, t 0..127
    k_tail4  <<<dim3(32, BO), 256>>>();                // T2 cols 128,129
    k_stage5 <<<dim3(8, 4, BO), 128>>>(bias, out);     // 1024 blocks, y 0..127
    k_tail5  <<<BO, 256>>>(bias, out);                 // out rows 128,129
}

// round 13
// speedup vs baseline: 1.6045x; 1.6045x over previous
#include <cuda_runtime.h>

// FourierConv2D via DFT-as-GEMM (fp32 FFMA) with five symmetry folds (~6.4 GFLOP):
//  1) real input => only ky=0..255 of the 511-row spectrum
//  2) forward col-DFT: P/Q shared-product pairs give F(kx), F(511-kx) together
//  3) inverse col-DFT K-fold: S=G+G', D=G-G' => K=256
//  4) inverse col-DFT x-fold: distinct x=0..127 (+tail 128/129), partner 257-t
//  5) row-inverse y-fold: distinct y=0..127 (+tail 128/129)
// R13: revert R12's register-prefetch double-buffering (regressed: spills).
// Back to the proven R10 two-sync loop, with K-chunk 16 -> 32 (halves BAR count;
// loader registers stay transient so ptxas pipelines as before).

namespace {
constexpr int N5    = 511;
constexpr int HH    = 256;
constexpr int NB    = 4;
constexpr int NCIN  = 4;
constexpr int NCOUT = 8;
constexpr int PLANE = N5 * N5;
constexpr int SQ    = HH * HH;       // 65536
constexpr int BC    = NB * NCIN;     // 16
constexpr int BO    = NB * NCOUT;    // 32
}

// ---- scratch (device globals) ----
__device__ float  g_Ar[SQ],  g_Ai[SQ];   // A[kx][n] = exp(-2pi i kx n/511)
__device__ float2 g_E[SQ];               // {Er,Ei}[x][kx] = exp(+2pi i kx (x+127)/511)/511
__device__ float  g_E5r[SQ], g_E5i[SQ];  // E5[y][ky] = w(ky) exp(+2pi i ky (y+127)/511)
__device__ float  g_T1r[BC*SQ], g_T1i[BC*SQ];
__device__ float2 g_P[BC*SQ], g_Q[BC*SQ];   // F(kx), F(511-kx), kx=0..255
__device__ float4 g_SD[BO*SQ];              // {Sr,Si,Dr,Di}[ky][kx]
__device__ float  g_T2r[BO*SQ], g_T2i[BO*SQ];

// ---- twiddle init ----
__global__ void k_twiddle() {
    const int idx = blockIdx.x * blockDim.x + threadIdx.x;   // 0..65535
    const float TWO_PI = 6.283185307179586f;
    const int r = idx >> 8, c = idx & 255;
    {   int m = (r * c) % N5;
        float s, co; sincosf(TWO_PI * (float)m / (float)N5, &s, &co);
        g_Ar[idx] = co;  g_Ai[idx] = -s;
    }
    {   int m = (c * (r + 127)) % N5;
        float s, co; sincosf(TWO_PI * (float)m / (float)N5, &s, &co);
        const float inv = 1.0f / (float)N5;
        g_E[idx] = make_float2(co * inv, s * inv);
    }
    {   int m = (c * (r + 127)) % N5;
        float s, co; sincosf(TWO_PI * (float)m / (float)N5, &s, &co);
        const float w = (c == 0) ? (1.0f / (float)N5) : (2.0f / (float)N5);
        g_E5r[idx] = co * w;  g_E5i[idx] = s * w;
    }
}

// All GEMM kernels: 32x32 tile, 128 threads, K-chunk 32, two syncs per chunk.

// ---- stage 1: T1[z] (256x256 cplx) = A[0:256] (cplx) @ X[z] (256x256 real) ----
__global__ void __launch_bounds__(128) k_stage1(const float* __restrict__ im) {
    const int z = blockIdx.z;
    const float* __restrict__ X = im + (size_t)z * SQ;
    float* __restrict__ Cr = g_T1r + (size_t)z * SQ;
    float* __restrict__ Ci = g_T1i + (size_t)z * SQ;

    __shared__ float Asr[32][36], Asi[32][36], Bs[32][36];
    const int tid = threadIdx.x;
    const int tx = tid & 15, ty = tid >> 4;
    const int m0 = blockIdx.y * 32, n0 = blockIdx.x * 32;
    const int ra = tid >> 2, ka = (tid & 3) * 4;
    const int kb = tid >> 3, nb = (tid & 7) * 4;

    float cr[4][2] = {}, ci[4][2] = {};

    for (int k0 = 0; k0 < HH; k0 += 32) {
        {   float4 a0 = *reinterpret_cast<const float4*>(g_Ar + (size_t)(m0 + ra)*HH + k0 + ka);
            float4 a1 = *reinterpret_cast<const float4*>(g_Ar + (size_t)(m0 + ra)*HH + k0 + ka + 16);
            float4 i0 = *reinterpret_cast<const float4*>(g_Ai + (size_t)(m0 + ra)*HH + k0 + ka);
            float4 i1 = *reinterpret_cast<const float4*>(g_Ai + (size_t)(m0 + ra)*HH + k0 + ka + 16);
            float4 b0 = *reinterpret_cast<const float4*>(X + (size_t)(k0 + kb)*HH + n0 + nb);
            float4 b1 = *reinterpret_cast<const float4*>(X + (size_t)(k0 + kb + 16)*HH + n0 + nb);
            Asr[ka+0][ra]=a0.x; Asr[ka+1][ra]=a0.y; Asr[ka+2][ra]=a0.z; Asr[ka+3][ra]=a0.w;
            Asr[ka+16][ra]=a1.x; Asr[ka+17][ra]=a1.y; Asr[ka+18][ra]=a1.z; Asr[ka+19][ra]=a1.w;
            Asi[ka+0][ra]=i0.x; Asi[ka+1][ra]=i0.y; Asi[ka+2][ra]=i0.z; Asi[ka+3][ra]=i0.w;
            Asi[ka+16][ra]=i1.x; Asi[ka+17][ra]=i1.y; Asi[ka+18][ra]=i1.z; Asi[ka+19][ra]=i1.w;
            Bs[kb][nb+0]=b0.x; Bs[kb][nb+1]=b0.y; Bs[kb][nb+2]=b0.z; Bs[kb][nb+3]=b0.w;
            Bs[kb+16][nb+0]=b1.x; Bs[kb+16][nb+1]=b1.y; Bs[kb+16][nb+2]=b1.z; Bs[kb+16][nb+3]=b1.w;
        }
        __syncthreads();

        #pragma unroll 4
        for (int k = 0; k < 32; k++) {
            float4 a_r = *reinterpret_cast<const float4*>(&Asr[k][ty*4]);
            float4 a_i = *reinterpret_cast<const float4*>(&Asi[k][ty*4]);
            float2 b   = *reinterpret_cast<const float2*>(&Bs[k][tx*2]);
            const float ar[4] = {a_r.x, a_r.y, a_r.z, a_r.w};
            const float ai[4] = {a_i.x, a_i.y, a_i.z, a_i.w};
            const float bb[2] = {b.x, b.y};
            #pragma unroll
            for (int i = 0; i < 4; i++)
                #pragma unroll
                for (int j = 0; j < 2; j++) {
                    cr[i][j] += ar[i] * bb[j];
                    ci[i][j] += ai[i] * bb[j];
                }
        }
        __syncthreads();
    }
    const int gn = n0 + tx*2;
    #pragma unroll
    for (int i = 0; i < 4; i++) {
        const int gm = m0 + ty*4 + i;
        *reinterpret_cast<float2*>(Cr + (size_t)gm*HH + gn) = make_float2(cr[i][0], cr[i][1]);
        *reinterpret_cast<float2*>(Ci + (size_t)gm*HH + gn) = make_float2(ci[i][0], ci[i][1]);
    }
}

// ---- stage 2: P,Q[z][ky][kx] via shared products U/V/X/Y ----
// P = (U-V, X+Y) = F(kx);  Q = (U+V, Y-X) = F(511-kx)
__global__ void __launch_bounds__(128) k_stage2() {
    const int z = blockIdx.z;
    const float* __restrict__ T1r = g_T1r + (size_t)z * SQ;
    const float* __restrict__ T1i = g_T1i + (size_t)z * SQ;
    float2* __restrict__ P = g_P + (size_t)z * SQ;
    float2* __restrict__ Q = g_Q + (size_t)z * SQ;

    __shared__ float Asr[32][36], Asi[32][36], Bsr[32][36], Bsi[32][36];
    const int tid = threadIdx.x;
    const int tx = tid & 15, ty = tid >> 4;
    const int m0 = blockIdx.y * 32, n0 = blockIdx.x * 32;
    const int ra = tid >> 2, ka = (tid & 3) * 4;

    float U[4][2] = {}, V[4][2] = {}, Xc[4][2] = {}, Yc[4][2] = {};

    for (int k0 = 0; k0 < HH; k0 += 32) {
        {   float4 a0 = *reinterpret_cast<const float4*>(T1r + (size_t)(m0 + ra)*HH + k0 + ka);
            float4 a1 = *reinterpret_cast<const float4*>(T1r + (size_t)(m0 + ra)*HH + k0 + ka + 16);
            float4 i0 = *reinterpret_cast<const float4*>(T1i + (size_t)(m0 + ra)*HH + k0 + ka);
            float4 i1 = *reinterpret_cast<const float4*>(T1i + (size_t)(m0 + ra)*HH + k0 + ka + 16);
            float4 b0 = *reinterpret_cast<const float4*>(g_Ar + (size_t)(n0 + ra)*HH + k0 + ka);
            float4 b1 = *reinterpret_cast<const float4*>(g_Ar + (size_t)(n0 + ra)*HH + k0 + ka + 16);
            float4 c0 = *reinterpret_cast<const float4*>(g_Ai + (size_t)(n0 + ra)*HH + k0 + ka);
            float4 c1 = *reinterpret_cast<const float4*>(g_Ai + (size_t)(n0 + ra)*HH + k0 + ka + 16);
            Asr[ka+0][ra]=a0.x; Asr[ka+1][ra]=a0.y; Asr[ka+2][ra]=a0.z; Asr[ka+3][ra]=a0.w;
            Asr[ka+16][ra]=a1.x; Asr[ka+17][ra]=a1.y; Asr[ka+18][ra]=a1.z; Asr[ka+19][ra]=a1.w;
            Asi[ka+0][ra]=i0.x; Asi[ka+1][ra]=i0.y; Asi[ka+2][ra]=i0.z; Asi[ka+3][ra]=i0.w;
            Asi[ka+16][ra]=i1.x; Asi[ka+17][ra]=i1.y; Asi[ka+18][ra]=i1.z; Asi[ka+19][ra]=i1.w;
            Bsr[ka+0][ra]=b0.x; Bsr[ka+1][ra]=b0.y; Bsr[ka+2][ra]=b0.z; Bsr[ka+3][ra]=b0.w;
            Bsr[ka+16][ra]=b1.x; Bsr[ka+17][ra]=b1.y; Bsr[ka+18][ra]=b1.z; Bsr[ka+19][ra]=b1.w;
            Bsi[ka+0][ra]=c0.x; Bsi[ka+1][ra]=c0.y; Bsi[ka+2][ra]=c0.z; Bsi[ka+3][ra]=c0.w;
            Bsi[ka+16][ra]=c1.x; Bsi[ka+17][ra]=c1.y; Bsi[ka+18][ra]=c1.z; Bsi[ka+19][ra]=c1.w;
        }
        __syncthreads();

        #pragma unroll 4
        for (int k = 0; k < 32; k++) {
            float4 a_r = *reinterpret_cast<const float4*>(&Asr[k][ty*4]);
            float4 a_i = *reinterpret_cast<const float4*>(&Asi[k][ty*4]);
            float2 b_r = *reinterpret_cast<const float2*>(&Bsr[k][tx*2]);
            float2 b_i = *reinterpret_cast<const float2*>(&Bsi[k][tx*2]);
            const float ar[4] = {a_r.x, a_r.y, a_r.z, a_r.w};
            const float ai[4] = {a_i.x, a_i.y, a_i.z, a_i.w};
            const float wr[2] = {b_r.x, b_r.y};
            const float wi[2] = {b_i.x, b_i.y};
            #pragma unroll
            for (int i = 0; i < 4; i++)
                #pragma unroll
                for (int j = 0; j < 2; j++) {
                    U [i][j] += ar[i] * wr[j];
                    V [i][j] += ai[i] * wi[j];
                    Xc[i][j] += ar[i] * wi[j];
                    Yc[i][j] += ai[i] * wr[j];
                }
        }
        __syncthreads();
    }
    const int gn = n0 + tx*2;
    #pragma unroll
    for (int i = 0; i < 4; i++) {
        const int gm = m0 + ty*4 + i;
        float4 pv = make_float4(U[i][0]-V[i][0], Xc[i][0]+Yc[i][0],
                                U[i][1]-V[i][1], Xc[i][1]+Yc[i][1]);
        float4 qv = make_float4(U[i][0]+V[i][0], Yc[i][0]-Xc[i][0],
                                U[i][1]+V[i][1], Yc[i][1]-Xc[i][1]);
        *reinterpret_cast<float4*>(P + (size_t)gm*HH + gn) = pv;
        *reinterpret_cast<float4*>(Q + (size_t)gm*HH + gn) = qv;
    }
}

// ---- stage 3: pointwise Hermitian-W multiply + cin sum + S/D combine ----
__global__ void k_pointwise(const float* __restrict__ w) {
    const int p = blockIdx.x * blockDim.x + threadIdx.x;  // ky*256+kx
    const int o = blockIdx.y;
    const int ky = p >> 8, kx = p & 255;
    const int ky2 = (N5 - ky) % N5;
    const int kx2 = (N5 - kx) % N5;

    float2 wh1[NCIN], wh2[NCIN];
    #pragma unroll
    for (int c = 0; c < NCIN; c++) {
        const float* wb = w + (size_t)(o*NCIN + c) * PLANE * 2;
        const float2 a = *reinterpret_cast<const float2*>(wb + ((size_t)ky *N5 + kx )*2);
        const float2 bq= *reinterpret_cast<const float2*>(wb + ((size_t)ky2*N5 + kx2)*2);
        wh1[c] = make_float2(0.5f*(a.x + bq.x), 0.5f*(a.y - bq.y));
        if (kx != 0) {
            const float2 e = *reinterpret_cast<const float2*>(wb + ((size_t)ky *N5 + (N5-kx))*2);
            const float2 f = *reinterpret_cast<const float2*>(wb + ((size_t)ky2*N5 + kx     )*2);
            wh2[c] = make_float2(0.5f*(e.x + f.x), 0.5f*(e.y - f.y));
        } else {
            wh2[c] = make_float2(0.f, 0.f);
        }
    }
    #pragma unroll
    for (int b = 0; b < NB; b++) {
        float gr = 0.f, gi = 0.f, hr = 0.f, hi = 0.f;
        #pragma unroll
        for (int c = 0; c < NCIN; c++) {
            const float2 Pv = g_P[(size_t)(b*NCIN + c)*SQ + p];
            const float2 Qv = g_Q[(size_t)(b*NCIN + c)*SQ + p];
            gr += Pv.x * wh1[c].x - Pv.y * wh1[c].y;
            gi += Pv.x * wh1[c].y + Pv.y * wh1[c].x;
            hr += Qv.x * wh2[c].x - Qv.y * wh2[c].y;
            hi += Qv.x * wh2[c].y + Qv.y * wh2[c].x;
        }
        g_SD[(size_t)(b*NCOUT + o)*SQ + p] =
            make_float4(gr + hr, gi + hi, gr - hr, gi - hi);
    }
}

// ---- stage 4 (x-folded): distinct cols t=0..127, partners x=257-t (t>=2) ----
// P=Sum Sr*Er, Q=Sum Di*Ei, R=Sum Si*Er, T=Sum Dr*Ei  over kx
// T2[ky][t] = (P-Q, R+T);  T2[ky][257-t] = (P+Q, R-T)
__global__ void __launch_bounds__(128) k_stage4() {
    const int z = blockIdx.z;
    const float4* __restrict__ Ag = g_SD + (size_t)z * SQ;
    float* __restrict__ Cr = g_T2r + (size_t)z * SQ;
    float* __restrict__ Ci = g_T2i + (size_t)z * SQ;

    __shared__ float4 As4[32][33];    // float4 elems -> 16B aligned
    __shared__ float2 Bs2[32][34];    // row 272B = 17*16 (float4-read safe)
    const int tid = threadIdx.x;
    const int tx = tid & 15, ty = tid >> 4;
    const int m0 = blockIdx.y * 32, n0 = blockIdx.x * 32;
    const int ra = tid >> 2, ka = (tid & 3) * 4;

    float P[4][2] = {}, Q[4][2] = {}, R[4][2] = {}, T[4][2] = {};

    for (int k0 = 0; k0 < HH; k0 += 32) {
        #pragma unroll
        for (int j = 0; j < 4; j++) {
            As4[ka + j][ra]      = Ag[(size_t)(m0 + ra)*HH + k0 + ka + j];
            As4[ka + 16 + j][ra] = Ag[(size_t)(m0 + ra)*HH + k0 + ka + 16 + j];
        }
        {   const float4* src = reinterpret_cast<const float4*>(g_E + (size_t)(n0 + ra)*HH + k0 + ka);
            float4 e01 = src[0], e23 = src[1];
            const float4* src2 = reinterpret_cast<const float4*>(g_E + (size_t)(n0 + ra)*HH + k0 + ka + 16);
            float4 f01 = src2[0], f23 = src2[1];
            Bs2[ka+0][ra] = make_float2(e01.x, e01.y);
            Bs2[ka+1][ra] = make_float2(e01.z, e01.w);
            Bs2[ka+2][ra] = make_float2(e23.x, e23.y);
            Bs2[ka+3][ra] = make_float2(e23.z, e23.w);
            Bs2[ka+16][ra] = make_float2(f01.x, f01.y);
            Bs2[ka+17][ra] = make_float2(f01.z, f01.w);
            Bs2[ka+18][ra] = make_float2(f23.x, f23.y);
            Bs2[ka+19][ra] = make_float2(f23.z, f23.w);
        }
        __syncthreads();

        #pragma unroll 2
        for (int k = 0; k < 32; k++) {
            float4 a[4];
            #pragma unroll
            for (int i = 0; i < 4; i++) a[i] = As4[k][ty*4 + i];
            float4 bvec = *reinterpret_cast<const float4*>(&Bs2[k][tx*2]);  // {Er0,Ei0,Er1,Ei1}
            const float er[2] = {bvec.x, bvec.z};
            const float ei[2] = {bvec.y, bvec.w};
            #pragma unroll
            for (int i = 0; i < 4; i++)
                #pragma unroll
                for (int j = 0; j < 2; j++) {
                    P[i][j] += a[i].x * er[j];   // Sr*Er
                    Q[i][j] += a[i].w * ei[j];   // Di*Ei
                    R[i][j] += a[i].y * er[j];   // Si*Er
                    T[i][j] += a[i].z * ei[j];   // Dr*Ei
                }
        }
        __syncthreads();
    }
    const int t0 = n0 + tx*2;
    #pragma unroll
    for (int i = 0; i < 4; i++) {
        const int gm = m0 + ty*4 + i;
        *reinterpret_cast<float2*>(Cr + (size_t)gm*HH + t0) =
            make_float2(P[i][0]-Q[i][0], P[i][1]-Q[i][1]);
        *reinterpret_cast<float2*>(Ci + (size_t)gm*HH + t0) =
            make_float2(R[i][0]+T[i][0], R[i][1]+T[i][1]);
        if (t0 >= 2) {
            *reinterpret_cast<float2*>(Cr + (size_t)gm*HH + 256 - t0) =
                make_float2(P[i][1]+Q[i][1], P[i][0]+Q[i][0]);
            *reinterpret_cast<float2*>(Ci + (size_t)gm*HH + 256 - t0) =
                make_float2(R[i][1]-T[i][1], R[i][0]-T[i][0]);
        }
    }
}

// ---- stage 4 tail: T2 cols 128,129 from E row 128 (129 = conj partner) ----
__global__ void k_tail4() {
    const int z = blockIdx.y;
    const int warp = threadIdx.x >> 5, lane = threadIdx.x & 31;
    const int ky = blockIdx.x * 8 + warp;
    const float4* __restrict__ Arow = g_SD + (size_t)z * SQ + (size_t)ky * HH;
    float P = 0.f, Q = 0.f, R = 0.f, T = 0.f;
    for (int kx = lane; kx < HH; kx += 32) {
        const float4 a = Arow[kx];
        const float2 e = g_E[128*HH + kx];
        P += a.x * e.x;  Q += a.w * e.y;
        R += a.y * e.x;  T += a.z * e.y;
    }
    #pragma unroll
    for (int off = 16; off; off >>= 1) {
        P += __shfl_down_sync(0xffffffffu, P, off);
        Q += __shfl_down_sync(0xffffffffu, Q, off);
        R += __shfl_down_sync(0xffffffffu, R, off);
        T += __shfl_down_sync(0xffffffffu, T, off);
    }
    if (lane == 0) {
        float* Cr = g_T2r + (size_t)z * SQ + (size_t)ky * HH;
        float* Ci = g_T2i + (size_t)z * SQ + (size_t)ky * HH;
        Cr[128] = P - Q;  Ci[128] = R + T;
        Cr[129] = P + Q;  Ci[129] = R - T;
    }
}

// ---- stage 5 (y-folded): distinct rows y=0..127, partners 257-y (y>=2) ----
// P=Sum E5r*T2r, Q=Sum E5i*T2i;  out[y]=P-Q+b;  out[257-y]=P+Q+b
__global__ void __launch_bounds__(128) k_stage5(const float* __restrict__ bias,
                                                float* __restrict__ out) {
    const int z = blockIdx.z;
    const float* __restrict__ Br = g_T2r + (size_t)z * SQ;
    const float* __restrict__ Bi = g_T2i + (size_t)z * SQ;
    float* __restrict__ O = out + (size_t)z * SQ;

    __shared__ float Asr[32][36], Asi[32][36], Bsr[32][36], Bsi[32][36];
    const int tid = threadIdx.x;
    const int tx = tid & 15, ty = tid >> 4;
    const int m0 = blockIdx.y * 32, n0 = blockIdx.x * 32;  // m0 in {0,32,64,96}
    const int ra = tid >> 2, ka = (tid & 3) * 4;
    const int kb = tid >> 3, nb = (tid & 7) * 4;

    float P[4][2] = {}, Q[4][2] = {};

    for (int k0 = 0; k0 < HH; k0 += 32) {
        {   float4 a0 = *reinterpret_cast<const float4*>(g_E5r + (size_t)(m0 + ra)*HH + k0 + ka);
            float4 a1 = *reinterpret_cast<const float4*>(g_E5r + (size_t)(m0 + ra)*HH + k0 + ka + 16);
            float4 i0 = *reinterpret_cast<const float4*>(g_E5i + (size_t)(m0 + ra)*HH + k0 + ka);
            float4 i1 = *reinterpret_cast<const float4*>(g_E5i + (size_t)(m0 + ra)*HH + k0 + ka + 16);
            float4 b0 = *reinterpret_cast<const float4*>(Br + (size_t)(k0 + kb)*HH + n0 + nb);
            float4 b1 = *reinterpret_cast<const float4*>(Br + (size_t)(k0 + kb + 16)*HH + n0 + nb);
            float4 c0 = *reinterpret_cast<const float4*>(Bi + (size_t)(k0 + kb)*HH + n0 + nb);
            float4 c1 = *reinterpret_cast<const float4*>(Bi + (size_t)(k0 + kb + 16)*HH + n0 + nb);
            Asr[ka+0][ra]=a0.x; Asr[ka+1][ra]=a0.y; Asr[ka+2][ra]=a0.z; Asr[ka+3][ra]=a0.w;
            Asr[ka+16][ra]=a1.x; Asr[ka+17][ra]=a1.y; Asr[ka+18][ra]=a1.z; Asr[ka+19][ra]=a1.w;
            Asi[ka+0][ra]=i0.x; Asi[ka+1][ra]=i0.y; Asi[ka+2][ra]=i0.z; Asi[ka+3][ra]=i0.w;
            Asi[ka+16][ra]=i1.x; Asi[ka+17][ra]=i1.y; Asi[ka+18][ra]=i1.z; Asi[ka+19][ra]=i1.w;
            Bsr[kb][nb+0]=b0.x; Bsr[kb][nb+1]=b0.y; Bsr[kb][nb+2]=b0.z; Bsr[kb][nb+3]=b0.w;
            Bsr[kb+16][nb+0]=b1.x; Bsr[kb+16][nb+1]=b1.y; Bsr[kb+16][nb+2]=b1.z; Bsr[kb+16][nb+3]=b1.w;
            Bsi[kb][nb+0]=c0.x; Bsi[kb][nb+1]=c0.y; Bsi[kb][nb+2]=c0.z; Bsi[kb][nb+3]=c0.w;
            Bsi[kb+16][nb+0]=c1.x; Bsi[kb+16][nb+1]=c1.y; Bsi[kb+16][nb+2]=c1.z; Bsi[kb+16][nb+3]=c1.w;
        }
        __syncthreads();

        #pragma unroll 4
        for (int k = 0; k < 32; k++) {
            float4 e_r = *reinterpret_cast<const float4*>(&Asr[k][ty*4]);
            float4 e_i = *reinterpret_cast<const float4*>(&Asi[k][ty*4]);
            float2 b_r = *reinterpret_cast<const float2*>(&Bsr[k][tx*2]);
            float2 b_i = *reinterpret_cast<const float2*>(&Bsi[k][tx*2]);
            const float er[4] = {e_r.x, e_r.y, e_r.z, e_r.w};
            const float ei[4] = {e_i.x, e_i.y, e_i.z, e_i.w};
            const float br[2] = {b_r.x, b_r.y};
            const float bi[2] = {b_i.x, b_i.y};
            #pragma unroll
            for (int i = 0; i < 4; i++)
                #pragma unroll
                for (int j = 0; j < 2; j++) {
                    P[i][j] += er[i] * br[j];
                    Q[i][j] += ei[i] * bi[j];
                }
        }
        __syncthreads();
    }
    const float bv = bias[z & 7];
    const int gn = n0 + tx*2;
    #pragma unroll
    for (int i = 0; i < 4; i++) {
        const int gm = m0 + ty*4 + i;   // 0..127
        *reinterpret_cast<float2*>(&O[(size_t)gm*HH + gn]) =
            make_float2(P[i][0]-Q[i][0] + bv, P[i][1]-Q[i][1] + bv);
        if (gm >= 2) {
            *reinterpret_cast<float2*>(&O[(size_t)(257 - gm)*HH + gn]) =
                make_float2(P[i][0]+Q[i][0] + bv, P[i][1]+Q[i][1] + bv);
        }
    }
}

// ---- stage 5 tail: out rows 128,129 from E5 row 128 (129 = conj partner) ----
__global__ void k_tail5(const float* __restrict__ bias, float* __restrict__ out) {
    const int z = blockIdx.x;
    const int n = threadIdx.x;
    const float* __restrict__ Br = g_T2r + (size_t)z * SQ;
    const float* __restrict__ Bi = g_T2i + (size_t)z * SQ;
    float P = 0.f, Q = 0.f;
    for (int ky = 0; ky < HH; ky++) {
        P += g_E5r[128*HH + ky] * Br[(size_t)ky*HH + n];
        Q += g_E5i[128*HH + ky] * Bi[(size_t)ky*HH + n];
    }
    const float bv = bias[z & 7];
    out[(size_t)z*SQ + 128*HH + n] = P - Q + bv;
    out[(size_t)z*SQ + 129*HH + n] = P + Q + bv;
}

extern "C" void kernel_launch(void* const* d_in, const int* in_sizes, int n_in,
                              void* d_out, int out_size) {
    (void)in_sizes; (void)n_in; (void)out_size;
    const float* im   = (const float*)d_in[0];  // [4,4,256,256]
    const float* w    = (const float*)d_in[1];  // [8,4,511,511,2]
    const float* bias = (const float*)d_in[2];  // [8,1,1]
    float* out = (float*)d_out;                 // [4,8,256,256]

    k_twiddle<<<256, 256>>>();
    k_stage1 <<<dim3(8, 8, BC), 128>>>(im);            // 1024 blocks
    k_stage2 <<<dim3(8, 8, BC), 128>>>();              // 1024 blocks
    k_pointwise<<<dim3(SQ / 256, NCOUT), 256>>>(w);
    k_stage4 <<<dim3(4, 8, BO), 128>>>();              // 1024 blocks, t 0..127
    k_tail4  <<<dim3(32, BO), 256>>>();                // T2 cols 128,129
    k_stage5 <<<dim3(8, 4, BO), 128>>>(bias, out);     // 1024 blocks, y 0..127
    k_tail5  <<<BO, 256>>>(bias, out);                 // out rows 128,129
}

// round 14
// speedup vs baseline: 1.7050x; 1.0626x over previous
#include <cuda_runtime.h>

// FourierConv2D via DFT-as-GEMM (fp32 FFMA) with five symmetry folds (~6.4 GFLOP):
//  1) real input => only ky=0..255 of the 511-row spectrum
//  2) forward col-DFT: P/Q shared-product pairs give F(kx), F(511-kx) together
//  3) inverse col-DFT K-fold: S=G+G', D=G-G' => K=256
//  4) inverse col-DFT x-fold: distinct x=0..127 (+tail 128/129), partner 257-t
//  5) row-inverse y-fold: distinct y=0..127 (+tail 128/129)
// R14: tail kernels folded into stage4/stage5 as extra grid slices (2 fewer
// launches; tails overlap main-stage wave tails). GEMM config = proven R13:
// 32x32 tiles, 128 threads, K-chunk 32, two syncs per chunk.

namespace {
constexpr int N5    = 511;
constexpr int HH    = 256;
constexpr int NB    = 4;
constexpr int NCIN  = 4;
constexpr int NCOUT = 8;
constexpr int PLANE = N5 * N5;
constexpr int SQ    = HH * HH;       // 65536
constexpr int BC    = NB * NCIN;     // 16
constexpr int BO    = NB * NCOUT;    // 32
}

// ---- scratch (device globals) ----
__device__ float  g_Ar[SQ],  g_Ai[SQ];   // A[kx][n] = exp(-2pi i kx n/511)
__device__ float2 g_E[SQ];               // {Er,Ei}[x][kx] = exp(+2pi i kx (x+127)/511)/511
__device__ float  g_E5r[SQ], g_E5i[SQ];  // E5[y][ky] = w(ky) exp(+2pi i ky (y+127)/511)
__device__ float  g_T1r[BC*SQ], g_T1i[BC*SQ];
__device__ float2 g_P[BC*SQ], g_Q[BC*SQ];   // F(kx), F(511-kx), kx=0..255
__device__ float4 g_SD[BO*SQ];              // {Sr,Si,Dr,Di}[ky][kx]
__device__ float  g_T2r[BO*SQ], g_T2i[BO*SQ];

// ---- twiddle init ----
__global__ void k_twiddle() {
    const int idx = blockIdx.x * blockDim.x + threadIdx.x;   // 0..65535
    const float TWO_PI = 6.283185307179586f;
    const int r = idx >> 8, c = idx & 255;
    {   int m = (r * c) % N5;
        float s, co; sincosf(TWO_PI * (float)m / (float)N5, &s, &co);
        g_Ar[idx] = co;  g_Ai[idx] = -s;
    }
    {   int m = (c * (r + 127)) % N5;
        float s, co; sincosf(TWO_PI * (float)m / (float)N5, &s, &co);
        const float inv = 1.0f / (float)N5;
        g_E[idx] = make_float2(co * inv, s * inv);
    }
    {   int m = (c * (r + 127)) % N5;
        float s, co; sincosf(TWO_PI * (float)m / (float)N5, &s, &co);
        const float w = (c == 0) ? (1.0f / (float)N5) : (2.0f / (float)N5);
        g_E5r[idx] = co * w;  g_E5i[idx] = s * w;
    }
}

// ---- stage 1: T1[z] (256x256 cplx) = A[0:256] (cplx) @ X[z] (256x256 real) ----
__global__ void __launch_bounds__(128) k_stage1(const float* __restrict__ im) {
    const int z = blockIdx.z;
    const float* __restrict__ X = im + (size_t)z * SQ;
    float* __restrict__ Cr = g_T1r + (size_t)z * SQ;
    float* __restrict__ Ci = g_T1i + (size_t)z * SQ;

    __shared__ float Asr[32][36], Asi[32][36], Bs[32][36];
    const int tid = threadIdx.x;
    const int tx = tid & 15, ty = tid >> 4;
    const int m0 = blockIdx.y * 32, n0 = blockIdx.x * 32;
    const int ra = tid >> 2, ka = (tid & 3) * 4;
    const int kb = tid >> 3, nb = (tid & 7) * 4;

    float cr[4][2] = {}, ci[4][2] = {};

    for (int k0 = 0; k0 < HH; k0 += 32) {
        {   float4 a0 = *reinterpret_cast<const float4*>(g_Ar + (size_t)(m0 + ra)*HH + k0 + ka);
            float4 a1 = *reinterpret_cast<const float4*>(g_Ar + (size_t)(m0 + ra)*HH + k0 + ka + 16);
            float4 i0 = *reinterpret_cast<const float4*>(g_Ai + (size_t)(m0 + ra)*HH + k0 + ka);
            float4 i1 = *reinterpret_cast<const float4*>(g_Ai + (size_t)(m0 + ra)*HH + k0 + ka + 16);
            float4 b0 = *reinterpret_cast<const float4*>(X + (size_t)(k0 + kb)*HH + n0 + nb);
            float4 b1 = *reinterpret_cast<const float4*>(X + (size_t)(k0 + kb + 16)*HH + n0 + nb);
            Asr[ka+0][ra]=a0.x; Asr[ka+1][ra]=a0.y; Asr[ka+2][ra]=a0.z; Asr[ka+3][ra]=a0.w;
            Asr[ka+16][ra]=a1.x; Asr[ka+17][ra]=a1.y; Asr[ka+18][ra]=a1.z; Asr[ka+19][ra]=a1.w;
            Asi[ka+0][ra]=i0.x; Asi[ka+1][ra]=i0.y; Asi[ka+2][ra]=i0.z; Asi[ka+3][ra]=i0.w;
            Asi[ka+16][ra]=i1.x; Asi[ka+17][ra]=i1.y; Asi[ka+18][ra]=i1.z; Asi[ka+19][ra]=i1.w;
            Bs[kb][nb+0]=b0.x; Bs[kb][nb+1]=b0.y; Bs[kb][nb+2]=b0.z; Bs[kb][nb+3]=b0.w;
            Bs[kb+16][nb+0]=b1.x; Bs[kb+16][nb+1]=b1.y; Bs[kb+16][nb+2]=b1.z; Bs[kb+16][nb+3]=b1.w;
        }
        __syncthreads();

        #pragma unroll 4
        for (int k = 0; k < 32; k++) {
            float4 a_r = *reinterpret_cast<const float4*>(&Asr[k][ty*4]);
            float4 a_i = *reinterpret_cast<const float4*>(&Asi[k][ty*4]);
            float2 b   = *reinterpret_cast<const float2*>(&Bs[k][tx*2]);
            const float ar[4] = {a_r.x, a_r.y, a_r.z, a_r.w};
            const float ai[4] = {a_i.x, a_i.y, a_i.z, a_i.w};
            const float bb[2] = {b.x, b.y};
            #pragma unroll
            for (int i = 0; i < 4; i++)
                #pragma unroll
                for (int j = 0; j < 2; j++) {
                    cr[i][j] += ar[i] * bb[j];
                    ci[i][j] += ai[i] * bb[j];
                }
        }
        __syncthreads();
    }
    const int gn = n0 + tx*2;
    #pragma unroll
    for (int i = 0; i < 4; i++) {
        const int gm = m0 + ty*4 + i;
        *reinterpret_cast<float2*>(Cr + (size_t)gm*HH + gn) = make_float2(cr[i][0], cr[i][1]);
        *reinterpret_cast<float2*>(Ci + (size_t)gm*HH + gn) = make_float2(ci[i][0], ci[i][1]);
    }
}

// ---- stage 2: P,Q[z][ky][kx] via shared products U/V/X/Y ----
// P = (U-V, X+Y) = F(kx);  Q = (U+V, Y-X) = F(511-kx)
__global__ void __launch_bounds__(128) k_stage2() {
    const int z = blockIdx.z;
    const float* __restrict__ T1r = g_T1r + (size_t)z * SQ;
    const float* __restrict__ T1i = g_T1i + (size_t)z * SQ;
    float2* __restrict__ P = g_P + (size_t)z * SQ;
    float2* __restrict__ Q = g_Q + (size_t)z * SQ;

    __shared__ float Asr[32][36], Asi[32][36], Bsr[32][36], Bsi[32][36];
    const int tid = threadIdx.x;
    const int tx = tid & 15, ty = tid >> 4;
    const int m0 = blockIdx.y * 32, n0 = blockIdx.x * 32;
    const int ra = tid >> 2, ka = (tid & 3) * 4;

    float U[4][2] = {}, V[4][2] = {}, Xc[4][2] = {}, Yc[4][2] = {};

    for (int k0 = 0; k0 < HH; k0 += 32) {
        {   float4 a0 = *reinterpret_cast<const float4*>(T1r + (size_t)(m0 + ra)*HH + k0 + ka);
            float4 a1 = *reinterpret_cast<const float4*>(T1r + (size_t)(m0 + ra)*HH + k0 + ka + 16);
            float4 i0 = *reinterpret_cast<const float4*>(T1i + (size_t)(m0 + ra)*HH + k0 + ka);
            float4 i1 = *reinterpret_cast<const float4*>(T1i + (size_t)(m0 + ra)*HH + k0 + ka + 16);
            float4 b0 = *reinterpret_cast<const float4*>(g_Ar + (size_t)(n0 + ra)*HH + k0 + ka);
            float4 b1 = *reinterpret_cast<const float4*>(g_Ar + (size_t)(n0 + ra)*HH + k0 + ka + 16);
            float4 c0 = *reinterpret_cast<const float4*>(g_Ai + (size_t)(n0 + ra)*HH + k0 + ka);
            float4 c1 = *reinterpret_cast<const float4*>(g_Ai + (size_t)(n0 + ra)*HH + k0 + ka + 16);
            Asr[ka+0][ra]=a0.x; Asr[ka+1][ra]=a0.y; Asr[ka+2][ra]=a0.z; Asr[ka+3][ra]=a0.w;
            Asr[ka+16][ra]=a1.x; Asr[ka+17][ra]=a1.y; Asr[ka+18][ra]=a1.z; Asr[ka+19][ra]=a1.w;
            Asi[ka+0][ra]=i0.x; Asi[ka+1][ra]=i0.y; Asi[ka+2][ra]=i0.z; Asi[ka+3][ra]=i0.w;
            Asi[ka+16][ra]=i1.x; Asi[ka+17][ra]=i1.y; Asi[ka+18][ra]=i1.z; Asi[ka+19][ra]=i1.w;
            Bsr[ka+0][ra]=b0.x; Bsr[ka+1][ra]=b0.y; Bsr[ka+2][ra]=b0.z; Bsr[ka+3][ra]=b0.w;
            Bsr[ka+16][ra]=b1.x; Bsr[ka+17][ra]=b1.y; Bsr[ka+18][ra]=b1.z; Bsr[ka+19][ra]=b1.w;
            Bsi[ka+0][ra]=c0.x; Bsi[ka+1][ra]=c0.y; Bsi[ka+2][ra]=c0.z; Bsi[ka+3][ra]=c0.w;
            Bsi[ka+16][ra]=c1.x; Bsi[ka+17][ra]=c1.y; Bsi[ka+18][ra]=c1.z; Bsi[ka+19][ra]=c1.w;
        }
        __syncthreads();

        #pragma unroll 4
        for (int k = 0; k < 32; k++) {
            float4 a_r = *reinterpret_cast<const float4*>(&Asr[k][ty*4]);
            float4 a_i = *reinterpret_cast<const float4*>(&Asi[k][ty*4]);
            float2 b_r = *reinterpret_cast<const float2*>(&Bsr[k][tx*2]);
            float2 b_i = *reinterpret_cast<const float2*>(&Bsi[k][tx*2]);
            const float ar[4] = {a_r.x, a_r.y, a_r.z, a_r.w};
            const float ai[4] = {a_i.x, a_i.y, a_i.z, a_i.w};
            const float wr[2] = {b_r.x, b_r.y};
            const float wi[2] = {b_i.x, b_i.y};
            #pragma unroll
            for (int i = 0; i < 4; i++)
                #pragma unroll
                for (int j = 0; j < 2; j++) {
                    U [i][j] += ar[i] * wr[j];
                    V [i][j] += ai[i] * wi[j];
                    Xc[i][j] += ar[i] * wi[j];
                    Yc[i][j] += ai[i] * wr[j];
                }
        }
        __syncthreads();
    }
    const int gn = n0 + tx*2;
    #pragma unroll
    for (int i = 0; i < 4; i++) {
        const int gm = m0 + ty*4 + i;
        float4 pv = make_float4(U[i][0]-V[i][0], Xc[i][0]+Yc[i][0],
                                U[i][1]-V[i][1], Xc[i][1]+Yc[i][1]);
        float4 qv = make_float4(U[i][0]+V[i][0], Yc[i][0]-Xc[i][0],
                                U[i][1]+V[i][1], Yc[i][1]-Xc[i][1]);
        *reinterpret_cast<float4*>(P + (size_t)gm*HH + gn) = pv;
        *reinterpret_cast<float4*>(Q + (size_t)gm*HH + gn) = qv;
    }
}

// ---- stage 3: pointwise Hermitian-W multiply + cin sum + S/D combine ----
__global__ void k_pointwise(const float* __restrict__ w) {
    const int p = blockIdx.x * blockDim.x + threadIdx.x;  // ky*256+kx
    const int o = blockIdx.y;
    const int ky = p >> 8, kx = p & 255;
    const int ky2 = (N5 - ky) % N5;
    const int kx2 = (N5 - kx) % N5;

    float2 wh1[NCIN], wh2[NCIN];
    #pragma unroll
    for (int c = 0; c < NCIN; c++) {
        const float* wb = w + (size_t)(o*NCIN + c) * PLANE * 2;
        const float2 a = *reinterpret_cast<const float2*>(wb + ((size_t)ky *N5 + kx )*2);
        const float2 bq= *reinterpret_cast<const float2*>(wb + ((size_t)ky2*N5 + kx2)*2);
        wh1[c] = make_float2(0.5f*(a.x + bq.x), 0.5f*(a.y - bq.y));
        if (kx != 0) {
            const float2 e = *reinterpret_cast<const float2*>(wb + ((size_t)ky *N5 + (N5-kx))*2);
            const float2 f = *reinterpret_cast<const float2*>(wb + ((size_t)ky2*N5 + kx     )*2);
            wh2[c] = make_float2(0.5f*(e.x + f.x), 0.5f*(e.y - f.y));
        } else {
            wh2[c] = make_float2(0.f, 0.f);
        }
    }
    #pragma unroll
    for (int b = 0; b < NB; b++) {
        float gr = 0.f, gi = 0.f, hr = 0.f, hi = 0.f;
        #pragma unroll
        for (int c = 0; c < NCIN; c++) {
            const float2 Pv = g_P[(size_t)(b*NCIN + c)*SQ + p];
            const float2 Qv = g_Q[(size_t)(b*NCIN + c)*SQ + p];
            gr += Pv.x * wh1[c].x - Pv.y * wh1[c].y;
            gi += Pv.x * wh1[c].y + Pv.y * wh1[c].x;
            hr += Qv.x * wh2[c].x - Qv.y * wh2[c].y;
            hi += Qv.x * wh2[c].y + Qv.y * wh2[c].x;
        }
        g_SD[(size_t)(b*NCOUT + o)*SQ + p] =
            make_float4(gr + hr, gi + hi, gr - hr, gi - hi);
    }
}

// ---- stage 4 (x-folded): distinct cols t=0..127, partners x=257-t (t>=2) ----
// P=Sum Sr*Er, Q=Sum Di*Ei, R=Sum Si*Er, T=Sum Dr*Ei  over kx
// T2[ky][t] = (P-Q, R+T);  T2[ky][257-t] = (P+Q, R-T)
// grid.x slice 4 = fused tail: T2 cols 128,129 from E row 128 (129 = conj).
__global__ void __launch_bounds__(128) k_stage4() {
    const int z = blockIdx.z;
    const float4* __restrict__ Ag = g_SD + (size_t)z * SQ;
    float* __restrict__ Cr = g_T2r + (size_t)z * SQ;
    float* __restrict__ Ci = g_T2i + (size_t)z * SQ;
    const int m0 = blockIdx.y * 32;

    if (blockIdx.x == 4) {   // fused tail slice: 4 warps x 8 ky
        const int warp = threadIdx.x >> 5, lane = threadIdx.x & 31;
        for (int r = 0; r < 8; r++) {
            const int ky = m0 + warp * 8 + r;
            const float4* __restrict__ Arow = Ag + (size_t)ky * HH;
            float P = 0.f, Q = 0.f, R = 0.f, T = 0.f;
            for (int kx = lane; kx < HH; kx += 32) {
                const float4 a = Arow[kx];
                const float2 e = g_E[128*HH + kx];
                P += a.x * e.x;  Q += a.w * e.y;
                R += a.y * e.x;  T += a.z * e.y;
            }
            #pragma unroll
            for (int off = 16; off; off >>= 1) {
                P += __shfl_down_sync(0xffffffffu, P, off);
                Q += __shfl_down_sync(0xffffffffu, Q, off);
                R += __shfl_down_sync(0xffffffffu, R, off);
                T += __shfl_down_sync(0xffffffffu, T, off);
            }
            if (lane == 0) {
                Cr[(size_t)ky*HH + 128] = P - Q;  Ci[(size_t)ky*HH + 128] = R + T;
                Cr[(size_t)ky*HH + 129] = P + Q;  Ci[(size_t)ky*HH + 129] = R - T;
            }
        }
        return;
    }

    __shared__ float4 As4[32][33];    // float4 elems -> 16B aligned
    __shared__ float2 Bs2[32][34];    // row 272B = 17*16 (float4-read safe)
    const int tid = threadIdx.x;
    const int tx = tid & 15, ty = tid >> 4;
    const int n0 = blockIdx.x * 32;
    const int ra = tid >> 2, ka = (tid & 3) * 4;

    float P[4][2] = {}, Q[4][2] = {}, R[4][2] = {}, T[4][2] = {};

    for (int k0 = 0; k0 < HH; k0 += 32) {
        #pragma unroll
        for (int j = 0; j < 4; j++) {
            As4[ka + j][ra]      = Ag[(size_t)(m0 + ra)*HH + k0 + ka + j];
            As4[ka + 16 + j][ra] = Ag[(size_t)(m0 + ra)*HH + k0 + ka + 16 + j];
        }
        {   const float4* src = reinterpret_cast<const float4*>(g_E + (size_t)(n0 + ra)*HH + k0 + ka);
            float4 e01 = src[0], e23 = src[1];
            const float4* src2 = reinterpret_cast<const float4*>(g_E + (size_t)(n0 + ra)*HH + k0 + ka + 16);
            float4 f01 = src2[0], f23 = src2[1];
            Bs2[ka+0][ra] = make_float2(e01.x, e01.y);
            Bs2[ka+1][ra] = make_float2(e01.z, e01.w);
            Bs2[ka+2][ra] = make_float2(e23.x, e23.y);
            Bs2[ka+3][ra] = make_float2(e23.z, e23.w);
            Bs2[ka+16][ra] = make_float2(f01.x, f01.y);
            Bs2[ka+17][ra] = make_float2(f01.z, f01.w);
            Bs2[ka+18][ra] = make_float2(f23.x, f23.y);
            Bs2[ka+19][ra] = make_float2(f23.z, f23.w);
        }
        __syncthreads();

        #pragma unroll 2
        for (int k = 0; k < 32; k++) {
            float4 a[4];
            #pragma unroll
            for (int i = 0; i < 4; i++) a[i] = As4[k][ty*4 + i];
            float4 bvec = *reinterpret_cast<const float4*>(&Bs2[k][tx*2]);  // {Er0,Ei0,Er1,Ei1}
            const float er[2] = {bvec.x, bvec.z};
            const float ei[2] = {bvec.y, bvec.w};
            #pragma unroll
            for (int i = 0; i < 4; i++)
                #pragma unroll
                for (int j = 0; j < 2; j++) {
                    P[i][j] += a[i].x * er[j];   // Sr*Er
                    Q[i][j] += a[i].w * ei[j];   // Di*Ei
                    R[i][j] += a[i].y * er[j];   // Si*Er
                    T[i][j] += a[i].z * ei[j];   // Dr*Ei
                }
        }
        __syncthreads();
    }
    const int t0 = n0 + tx*2;
    #pragma unroll
    for (int i = 0; i < 4; i++) {
        const int gm = m0 + ty*4 + i;
        *reinterpret_cast<float2*>(Cr + (size_t)gm*HH + t0) =
            make_float2(P[i][0]-Q[i][0], P[i][1]-Q[i][1]);
        *reinterpret_cast<float2*>(Ci + (size_t)gm*HH + t0) =
            make_float2(R[i][0]+T[i][0], R[i][1]+T[i][1]);
        if (t0 >= 2) {
            *reinterpret_cast<float2*>(Cr + (size_t)gm*HH + 256 - t0) =
                make_float2(P[i][1]+Q[i][1], P[i][0]+Q[i][0]);
            *reinterpret_cast<float2*>(Ci + (size_t)gm*HH + 256 - t0) =
                make_float2(R[i][1]-T[i][1], R[i][0]-T[i][0]);
        }
    }
}

// ---- stage 5 (y-folded): distinct rows y=0..127, partners 257-y (y>=2) ----
// P=Sum E5r*T2r, Q=Sum E5i*T2i;  out[y]=P-Q+b;  out[257-y]=P+Q+b
// grid.x slice 8 = fused tail: out rows 128,129 (E5 row 128; 129 = conj).
__global__ void __launch_bounds__(128) k_stage5(const float* __restrict__ bias,
                                                float* __restrict__ out) {
    const int z = blockIdx.z;
    const float* __restrict__ Br = g_T2r + (size_t)z * SQ;
    const float* __restrict__ Bi = g_T2i + (size_t)z * SQ;
    float* __restrict__ O = out + (size_t)z * SQ;
    const float bv = bias[z & 7];

    if (blockIdx.x == 8) {   // fused tail slice: 64-col strip, rows 128/129
        const int t = threadIdx.x;
        if (t < 64) {
            const int n = blockIdx.y * 64 + t;
            float P = 0.f, Q = 0.f;
            for (int ky = 0; ky < HH; ky++) {
                P += g_E5r[128*HH + ky] * Br[(size_t)ky*HH + n];
                Q += g_E5i[128*HH + ky] * Bi[(size_t)ky*HH + n];
            }
            O[128*HH + n] = P - Q + bv;
            O[129*HH + n] = P + Q + bv;
        }
        return;
    }

    __shared__ float Asr[32][36], Asi[32][36], Bsr[32][36], Bsi[32][36];
    const int tid = threadIdx.x;
    const int tx = tid & 15, ty = tid >> 4;
    const int m0 = blockIdx.y * 32, n0 = blockIdx.x * 32;  // m0 in {0,32,64,96}
    const int ra = tid >> 2, ka = (tid & 3) * 4;
    const int kb = tid >> 3, nb = (tid & 7) * 4;

    float P[4][2] = {}, Q[4][2] = {};

    for (int k0 = 0; k0 < HH; k0 += 32) {
        {   float4 a0 = *reinterpret_cast<const float4*>(g_E5r + (size_t)(m0 + ra)*HH + k0 + ka);
            float4 a1 = *reinterpret_cast<const float4*>(g_E5r + (size_t)(m0 + ra)*HH + k0 + ka + 16);
            float4 i0 = *reinterpret_cast<const float4*>(g_E5i + (size_t)(m0 + ra)*HH + k0 + ka);
            float4 i1 = *reinterpret_cast<const float4*>(g_E5i + (size_t)(m0 + ra)*HH + k0 + ka + 16);
            float4 b0 = *reinterpret_cast<const float4*>(Br + (size_t)(k0 + kb)*HH + n0 + nb);
            float4 b1 = *reinterpret_cast<const float4*>(Br + (size_t)(k0 + kb + 16)*HH + n0 + nb);
            float4 c0 = *reinterpret_cast<const float4*>(Bi + (size_t)(k0 + kb)*HH + n0 + nb);
            float4 c1 = *reinterpret_cast<const float4*>(Bi + (size_t)(k0 + kb + 16)*HH + n0 + nb);
            Asr[ka+0][ra]=a0.x; Asr[ka+1][ra]=a0.y; Asr[ka+2][ra]=a0.z; Asr[ka+3][ra]=a0.w;
            Asr[ka+16][ra]=a1.x; Asr[ka+17][ra]=a1.y; Asr[ka+18][ra]=a1.z; Asr[ka+19][ra]=a1.w;
            Asi[ka+0][ra]=i0.x; Asi[ka+1][ra]=i0.y; Asi[ka+2][ra]=i0.z; Asi[ka+3][ra]=i0.w;
            Asi[ka+16][ra]=i1.x; Asi[ka+17][ra]=i1.y; Asi[ka+18][ra]=i1.z; Asi[ka+19][ra]=i1.w;
            Bsr[kb][nb+0]=b0.x; Bsr[kb][nb+1]=b0.y; Bsr[kb][nb+2]=b0.z; Bsr[kb][nb+3]=b0.w;
            Bsr[kb+16][nb+0]=b1.x; Bsr[kb+16][nb+1]=b1.y; Bsr[kb+16][nb+2]=b1.z; Bsr[kb+16][nb+3]=b1.w;
            Bsi[kb][nb+0]=c0.x; Bsi[kb][nb+1]=c0.y; Bsi[kb][nb+2]=c0.z; Bsi[kb][nb+3]=c0.w;
            Bsi[kb+16][nb+0]=c1.x; Bsi[kb+16][nb+1]=c1.y; Bsi[kb+16][nb+2]=c1.z; Bsi[kb+16][nb+3]=c1.w;
        }
        __syncthreads();

        #pragma unroll 4
        for (int k = 0; k < 32; k++) {
            float4 e_r = *reinterpret_cast<const float4*>(&Asr[k][ty*4]);
            float4 e_i = *reinterpret_cast<const float4*>(&Asi[k][ty*4]);
            float2 b_r = *reinterpret_cast<const float2*>(&Bsr[k][tx*2]);
            float2 b_i = *reinterpret_cast<const float2*>(&Bsi[k][tx*2]);
            const float er[4] = {e_r.x, e_r.y, e_r.z, e_r.w};
            const float ei[4] = {e_i.x, e_i.y, e_i.z, e_i.w};
            const float br[2] = {b_r.x, b_r.y};
            const float bi[2] = {b_i.x, b_i.y};
            #pragma unroll
            for (int i = 0; i < 4; i++)
                #pragma unroll
                for (int j = 0; j < 2; j++) {
                    P[i][j] += er[i] * br[j];
                    Q[i][j] += ei[i] * bi[j];
                }
        }
        __syncthreads();
    }
    const int gn = n0 + tx*2;
    #pragma unroll
    for (int i = 0; i < 4; i++) {
        const int gm = m0 + ty*4 + i;   // 0..127
        *reinterpret_cast<float2*>(&O[(size_t)gm*HH + gn]) =
            make_float2(P[i][0]-Q[i][0] + bv, P[i][1]-Q[i][1] + bv);
        if (gm >= 2) {
            *reinterpret_cast<float2*>(&O[(size_t)(257 - gm)*HH + gn]) =
                make_float2(P[i][0]+Q[i][0] + bv, P[i][1]+Q[i][1] + bv);
        }
    }
}

extern "C" void kernel_launch(void* const* d_in, const int* in_sizes, int n_in,
                              void* d_out, int out_size) {
    (void)in_sizes; (void)n_in; (void)out_size;
    const float* im   = (const float*)d_in[0];  // [4,4,256,256]
    const float* w    = (const float*)d_in[1];  // [8,4,511,511,2]
    const float* bias = (const float*)d_in[2];  // [8,1,1]
    float* out = (float*)d_out;                 // [4,8,256,256]

    k_twiddle<<<256, 256>>>();
    k_stage1 <<<dim3(8, 8, BC), 128>>>(im);            // 1024 blocks
    k_stage2 <<<dim3(8, 8, BC), 128>>>();              // 1024 blocks
    k_pointwise<<<dim3(SQ / 256, NCOUT), 256>>>(w);
    k_stage4 <<<dim3(5, 8, BO), 128>>>();              // slices 0-3 GEMM, 4 tail
    k_stage5 <<<dim3(9, 4, BO), 128>>>(bias, out);     // slices 0-7 GEMM, 8 tail
}